// round 6
// baseline (speedup 1.0000x reference)
#include <cuda_runtime.h>
#include <cuda_bf16.h>

#define NPTS  16384
#define NNBR  32
#define CIN   16
#define COUT  16
#define NB    16
#define GAMMA 10.0f
#define EPSF  1e-12f

// Scratch (allocation-free rule: __device__ globals)
__device__ float4 g_inputT[NPTS * 4];   // [n*4+q] : channels 4q..4q+3 of point n
__device__ float4 g_coords4[NPTS];      // padded coords

// ---------------------------------------------------------------------------
// Prep: transpose input (C,N)->(N,C) float4 rows (coalesced reads), pad coords.
// idx = q*NPTS + n so consecutive threads read consecutive n (coalesced).
// ---------------------------------------------------------------------------
__global__ void prep_kernel(const float* __restrict__ input,
                            const float* __restrict__ coords) {
    int idx = blockIdx.x * blockDim.x + threadIdx.x;   // 0 .. NPTS*4-1
    int q = idx >> 14;            // idx / NPTS   (NPTS = 2^14)
    int n = idx & (NPTS - 1);
    float4 v;
    v.x = input[(4 * q + 0) * NPTS + n];
    v.y = input[(4 * q + 1) * NPTS + n];
    v.z = input[(4 * q + 2) * NPTS + n];
    v.w = input[(4 * q + 3) * NPTS + n];
    g_inputT[n * 4 + q] = v;
    if (q == 0) {
        float4 c;
        c.x = coords[n * 3 + 0];
        c.y = coords[n * 3 + 1];
        c.z = coords[n * 3 + 2];
        c.w = 0.0f;
        g_coords4[n] = c;
    }
}

// ---------------------------------------------------------------------------
// Main: 4 lanes per point; lane t owns CHANNELS 4t..4t+3 across ALL 16 bases.
// acc[b] (float4) = A[b][4t..4t+3]. No shuffles in the hot loop: each lane
// loads its own channel quartet (coalesced 64B per point-group) and computes
// all 16 RBF weights itself (MUFU pipe, overlaps FMA).
// Exponent strength-reduced:
//   arg_b = NGL2*(r-c_b)^2 + log2(m)
//         = (NGL2*r^2 + log2m) + r*(-2*NGL2*c_b) + NGL2*c_b^2
//         = fma(r, cs_b, e0 + K_b)           [1 FADD(alu) + 1 FFMA(fma)]
// Epilogue: po[o] = sum_{b,j} W[o][4t+j][b] * acc[b].j  (W in smem),
// butterfly-reduce over the 4-lane group, lane t writes outputs 4t..4t+3.
// ---------------------------------------------------------------------------
__global__ __launch_bounds__(128, 4)
void conv_kernel(const float* __restrict__ W,
                 const float* __restrict__ centers,
                 const float* __restrict__ mask,
                 const int*   __restrict__ neighbors,
                 float*       __restrict__ out) {
    __shared__ float4 Wsm[COUT * CIN * 4];   // raw copy of W, 16KB

    const int tid = threadIdx.x;
    {
        const float4* W4 = (const float4*)W;
        #pragma unroll
        for (int j = 0; j < 8; j++)
            Wsm[tid + 128 * j] = W4[tid + 128 * j];
    }
    __syncthreads();

    const int t  = tid & 3;          // channel-quartet owner
    const int pl = tid >> 2;         // point within block (0..31)
    const int n  = blockIdx.x * 32 + pl;

    const float NGL2 = -GAMMA * 1.4426950408889634f;   // -gamma * log2(e)

    float cs[NB], K[NB];
    #pragma unroll
    for (int b = 0; b < NB; b++) {
        const float cb = __ldg(&centers[b]);
        cs[b] = -2.0f * NGL2 * cb;     // coefficient of r
        K[b]  = NGL2 * cb * cb;        // constant term
    }

    const float4 pc = g_coords4[n];

    float4 acc[NB];
    #pragma unroll
    for (int b = 0; b < NB; b++) acc[b] = make_float4(0.f, 0.f, 0.f, 0.f);

    const int4*   nb4 = (const int4*)(neighbors + n * NNBR);
    const float4* mk4 = (const float4*)(mask + n * NNBR);

    for (int kk = 0; kk < NNBR / 4; kk++) {      // 8 iterations
        const int4   nb = __ldg(&nb4[kk]);
        const float4 mk = __ldg(&mk4[kk]);
        const int   ns[4] = {nb.x, nb.y, nb.z, nb.w};
        const float ms[4] = {mk.x, mk.y, mk.z, mk.w};

        #pragma unroll
        for (int j = 0; j < 4; j++) {
            const int   nbr = ns[j];
            const float lm  = __log2f(ms[j]);      // fold mask into exponent
            const float4 cc = g_coords4[nbr];
            const float dx = cc.x - pc.x;
            const float dy = cc.y - pc.y;
            const float dz = cc.z - pc.z;
            const float r2 = fmaf(dx, dx, fmaf(dy, dy, fmaf(dz, dz, EPSF)));
            const float r  = sqrtf(r2);
            const float e0 = fmaf(NGL2, r2, lm);   // NGL2*r^2 + log2(m)
            const float4 xq = __ldg(&g_inputT[nbr * 4 + t]);  // own quartet

            #pragma unroll
            for (int b = 0; b < NB; b++) {
                const float u = exp2f(fmaf(r, cs[b], e0 + K[b]));
                acc[b].x = fmaf(u, xq.x, acc[b].x);
                acc[b].y = fmaf(u, xq.y, acc[b].y);
                acc[b].z = fmaf(u, xq.z, acc[b].z);
                acc[b].w = fmaf(u, xq.w, acc[b].w);
            }
        }
    }

    // Epilogue: contract with W. Lane t covers channels i = 4t+j.
    float po[4];
    #pragma unroll
    for (int o = 0; o < COUT; o++) {
        float s = 0.f;
        #pragma unroll
        for (int j = 0; j < 4; j++) {
            const float4* wr = &Wsm[(o * CIN + 4 * t + j) * 4];
            #pragma unroll
            for (int bb = 0; bb < 4; bb++) {
                const float4 w = wr[bb];
                const int b = 4 * bb;
                const float a0 = (j == 0) ? acc[b + 0].x : (j == 1) ? acc[b + 0].y : (j == 2) ? acc[b + 0].z : acc[b + 0].w;
                const float a1 = (j == 0) ? acc[b + 1].x : (j == 1) ? acc[b + 1].y : (j == 2) ? acc[b + 1].z : acc[b + 1].w;
                const float a2 = (j == 0) ? acc[b + 2].x : (j == 1) ? acc[b + 2].y : (j == 2) ? acc[b + 2].z : acc[b + 2].w;
                const float a3 = (j == 0) ? acc[b + 3].x : (j == 1) ? acc[b + 3].y : (j == 2) ? acc[b + 3].z : acc[b + 3].w;
                s = fmaf(w.x, a0, s);
                s = fmaf(w.y, a1, s);
                s = fmaf(w.z, a2, s);
                s = fmaf(w.w, a3, s);
            }
        }
        // all-reduce over the 4-lane group (channel partials)
        s += __shfl_xor_sync(0xFFFFFFFFu, s, 1, 4);
        s += __shfl_xor_sync(0xFFFFFFFFu, s, 2, 4);
        if ((o >> 2) == t) po[o & 3] = s;
    }

    #pragma unroll
    for (int j = 0; j < 4; j++)
        out[(4 * t + j) * NPTS + n] = po[j];
}

// ---------------------------------------------------------------------------
extern "C" void kernel_launch(void* const* d_in, const int* in_sizes, int n_in,
                              void* d_out, int out_size) {
    const float* input     = (const float*)d_in[0];   // (16, 16384)
    const float* coords    = (const float*)d_in[1];   // (16384, 3)
    const float* W         = (const float*)d_in[2];   // (16, 16, 16)
    const float* centers   = (const float*)d_in[3];   // (16,)
    const float* mask      = (const float*)d_in[4];   // (16384, 32)
    const int*   neighbors = (const int*)d_in[5];     // (16384, 32)
    float*       out       = (float*)d_out;           // (16, 16384)

    prep_kernel<<<(NPTS * 4) / 256, 256>>>(input, coords);
    conv_kernel<<<NPTS / 32, 128>>>(W, centers, mask, neighbors, out);
}